// round 2
// baseline (speedup 1.0000x reference)
#include <cuda_runtime.h>

#define N_IMG 8
#define HH 128
#define WW 128
#define CF 64

// Scratch buffers (allocation-free workaround per harness rules)
__device__ float g_H[N_IMG * CF * HH * WW];          // head output / skip / body result
__device__ float g_A[N_IMG * CF * HH * WW];          // resblock carry
__device__ float g_B[N_IMG * CF * HH * WW];          // resblock temp
__device__ float g_S[N_IMG * 100 * 256 * 256];       // pixel-shuffled super output

// ---------------------------------------------------------------------------
// Head: out = conv3x3(x - mean, head_w) + head_b      (3 -> 64 channels)
// ---------------------------------------------------------------------------
__global__ __launch_bounds__(256) void head_kernel(
    const float* __restrict__ x, const float* __restrict__ w,
    const float* __restrict__ b, float* __restrict__ out)
{
    int idx = blockIdx.x * 256 + threadIdx.x;
    if (idx >= N_IMG * CF * HH * WW) return;
    int px = idx & (WW - 1);
    int py = (idx >> 7) & (HH - 1);
    int oc = (idx >> 14) & 63;
    int n  = idx >> 20;

    const float mean[3] = {0.4488f * 255.0f, 0.4371f * 255.0f, 0.404f * 255.0f};
    float acc = b[oc];
    #pragma unroll
    for (int ic = 0; ic < 3; ic++) {
        const float* xin = x + ((n * 3 + ic) * HH) * WW;
        const float* wp  = w + (oc * 3 + ic) * 9;
        #pragma unroll
        for (int dy = 0; dy < 3; dy++) {
            int gy = py + dy - 1;
            if ((unsigned)gy >= HH) continue;
            #pragma unroll
            for (int dx = 0; dx < 3; dx++) {
                int gx = px + dx - 1;
                if ((unsigned)gx >= WW) continue;
                acc += (xin[gy * WW + gx] - mean[ic]) * wp[dy * 3 + dx];
            }
        }
    }
    out[idx] = acc;
}

// ---------------------------------------------------------------------------
// Main 3x3 conv, CIN=64, 64-oc chunk per block.
// Block = 128 threads, computes 64 oc x (16w x 4h) pixel tile.
// Thread = 4 oc x 8 px register tile.
// Templates: RELU epilogue, RESidual add (layout [N][64][H][W]),
//            SHUFfle epilogue (pixel-shuffle s=2 write into [N][100][256][256]).
// ---------------------------------------------------------------------------
template <bool RELU, bool RES, bool SHUF>
__global__ __launch_bounds__(128) void conv3x3_64(
    const float* __restrict__ in, const float* __restrict__ w,
    const float* __restrict__ bias, const float* __restrict__ res,
    float* __restrict__ out, int cout_total, int oc_chunks)
{
    __shared__ float in_s[8][6][18];      // 8 ic x (4+2) rows x (16+2) cols
    __shared__ float w_s[72][64];         // (8 ic * 9 taps) x 64 oc

    const int tid     = threadIdx.x;
    const int n       = blockIdx.z / oc_chunks;
    const int oc_base = (blockIdx.z % oc_chunks) * 64;
    const int x0      = blockIdx.x * 16;
    const int y0      = blockIdx.y * 4;
    const int oc_thr  = tid >> 3;         // 0..15  -> owns 4 oc
    const int px_thr  = tid & 7;          // 0..7   -> owns 8 px
    const int ty      = px_thr >> 1;      // row 0..3
    const int tx0     = (px_thr & 1) * 8; // col 0 or 8

    float acc[4][8];
    #pragma unroll
    for (int o = 0; o < 4; o++)
        #pragma unroll
        for (int j = 0; j < 8; j++) acc[o][j] = 0.f;

    for (int ic0 = 0; ic0 < 64; ic0 += 8) {
        // cooperative input tile load (zero-padded halo)
        for (int idx = tid; idx < 8 * 6 * 18; idx += 128) {
            int icl = idx / 108;
            int rem = idx - icl * 108;
            int r = rem / 18;
            int c = rem - r * 18;
            int gy = y0 + r - 1;
            int gx = x0 + c - 1;
            float v = 0.f;
            if ((unsigned)gy < HH && (unsigned)gx < WW)
                v = in[((n * 64 + ic0 + icl) * HH + gy) * WW + gx];
            in_s[icl][r][c] = v;
        }
        // cooperative weight load, transposed to [k][oc]
        for (int idx = tid; idx < 72 * 64; idx += 128) {
            int k   = idx >> 6;
            int oc  = idx & 63;
            int icl = k / 9;
            int tap = k - icl * 9;
            int ocg = oc_base + oc;
            float v = 0.f;
            if (ocg < cout_total)
                v = w[(ocg * 64 + ic0 + icl) * 9 + tap];
            w_s[k][oc] = v;
        }
        __syncthreads();

        #pragma unroll 2
        for (int icl = 0; icl < 8; icl++) {
            #pragma unroll
            for (int dy = 0; dy < 3; dy++) {
                float rv[10];
                #pragma unroll
                for (int c = 0; c < 10; c++) rv[c] = in_s[icl][ty + dy][tx0 + c];
                #pragma unroll
                for (int dx = 0; dx < 3; dx++) {
                    float4 wv = *(const float4*)&w_s[icl * 9 + dy * 3 + dx][oc_thr * 4];
                    #pragma unroll
                    for (int j = 0; j < 8; j++) {
                        float iv = rv[j + dx];
                        acc[0][j] += wv.x * iv;
                        acc[1][j] += wv.y * iv;
                        acc[2][j] += wv.z * iv;
                        acc[3][j] += wv.w * iv;
                    }
                }
            }
        }
        __syncthreads();
    }

    // epilogue
    #pragma unroll
    for (int o = 0; o < 4; o++) {
        int oc = oc_base + oc_thr * 4 + o;
        if (oc >= cout_total) continue;
        float bv = bias[oc];
        int yy = y0 + ty;
        #pragma unroll
        for (int j = 0; j < 8; j++) {
            int xx = x0 + tx0 + j;
            float v = acc[o][j] + bv;
            if (RELU) v = fmaxf(v, 0.f);
            if (RES)  v += res[((n * 64 + oc) * HH + yy) * WW + xx];
            if (SHUF) {
                int k = oc >> 2;
                int a = (oc >> 1) & 1;
                int bb = oc & 1;
                out[((n * 100 + k) * 256 + (yy * 2 + a)) * 256 + (xx * 2 + bb)] = v;
            } else {
                out[((n * 64 + oc) * HH + yy) * WW + xx] = v;
            }
        }
    }
}

// ---------------------------------------------------------------------------
// Tail: y = conv3x3(shuffled, out_w) + out_b + mean    (100 -> 3, 256x256)
// ---------------------------------------------------------------------------
__global__ __launch_bounds__(256) void tail_kernel(
    const float* __restrict__ in, const float* __restrict__ w,
    const float* __restrict__ b, float* __restrict__ out)
{
    __shared__ float w_s[2700];   // [3][100][9]
    for (int i = threadIdx.x; i < 2700; i += 256) w_s[i] = w[i];
    __syncthreads();

    int idx = blockIdx.x * 256 + threadIdx.x;   // over N*256*256
    int x = idx & 255;
    int y = (idx >> 8) & 255;
    int n = idx >> 16;

    float a0 = b[0], a1 = b[1], a2 = b[2];
    for (int ic = 0; ic < 100; ic++) {
        const float* ip = in + ((n * 100 + ic) * 256) * 256;
        #pragma unroll
        for (int dy = 0; dy < 3; dy++) {
            int gy = y + dy - 1;
            if ((unsigned)gy >= 256) continue;
            #pragma unroll
            for (int dx = 0; dx < 3; dx++) {
                int gx = x + dx - 1;
                if ((unsigned)gx >= 256) continue;
                float v = ip[gy * 256 + gx];
                int t = ic * 9 + dy * 3 + dx;
                a0 += v * w_s[t];
                a1 += v * w_s[900 + t];
                a2 += v * w_s[1800 + t];
            }
        }
    }
    const float m0 = 0.4488f * 255.0f, m1 = 0.4371f * 255.0f, m2 = 0.404f * 255.0f;
    out[((n * 3 + 0) * 256 + y) * 256 + x] = a0 + m0;
    out[((n * 3 + 1) * 256 + y) * 256 + x] = a1 + m1;
    out[((n * 3 + 2) * 256 + y) * 256 + x] = a2 + m2;
}

// ---------------------------------------------------------------------------
extern "C" void kernel_launch(void* const* d_in, const int* in_sizes, int n_in,
                              void* d_out, int out_size)
{
    const float* x       = (const float*)d_in[0];
    const float* head_w  = (const float*)d_in[1];
    const float* head_b  = (const float*)d_in[2];
    const float* rb_w1   = (const float*)d_in[3];
    const float* rb_b1   = (const float*)d_in[4];
    const float* rb_w2   = (const float*)d_in[5];
    const float* rb_b2   = (const float*)d_in[6];
    const float* body_w  = (const float*)d_in[7];
    const float* body_b  = (const float*)d_in[8];
    const float* super_w = (const float*)d_in[9];
    const float* super_b = (const float*)d_in[10];
    const float* out_w   = (const float*)d_in[11];
    const float* out_b   = (const float*)d_in[12];
    float* out = (float*)d_out;

    float *pH, *pA, *pB, *pS;
    cudaGetSymbolAddress((void**)&pH, g_H);
    cudaGetSymbolAddress((void**)&pA, g_A);
    cudaGetSymbolAddress((void**)&pB, g_B);
    cudaGetSymbolAddress((void**)&pS, g_S);

    // head
    head_kernel<<<(N_IMG * CF * HH * WW) / 256, 256>>>(x, head_w, head_b, pH);

    dim3 grid(WW / 16, HH / 4, N_IMG);

    // 16 residual blocks: B = relu(conv1(cur)); A = cur + conv2(B)
    const float* cur = pH;
    for (int i = 0; i < 16; i++) {
        conv3x3_64<true, false, false><<<grid, 128>>>(
            cur, rb_w1 + (size_t)i * 64 * 64 * 9, rb_b1 + i * 64, nullptr, pB, 64, 1);
        conv3x3_64<false, true, false><<<grid, 128>>>(
            pB, rb_w2 + (size_t)i * 64 * 64 * 9, rb_b2 + i * 64, cur, pA, 64, 1);
        cur = pA;
    }

    // body: H = conv(A) + H   (in-place residual on H is safe: H not conv input)
    conv3x3_64<false, true, false><<<grid, 128>>>(pA, body_w, body_b, pH, pH, 64, 1);

    // super conv 64 -> 400 with fused pixel shuffle (7 oc-chunks of 64)
    dim3 gridS(WW / 16, HH / 4, N_IMG * 7);
    conv3x3_64<false, false, true><<<gridS, 128>>>(pH, super_w, super_b, nullptr, pS, 400, 7);

    // tail conv 100 -> 3 on 256x256 + add mean
    tail_kernel<<<(N_IMG * 256 * 256) / 256, 256>>>(pS, out_w, out_b, out);
}